// round 13
// baseline (speedup 1.0000x reference)
#include <cuda_runtime.h>
#include <cuda_bf16.h>
#include <math.h>

// DescriptorBuilder: periodic minimum-image descriptors (O(N^2) factorized).
// Radial:  q_r[i,k] = sum_j fc(r_ij) * r_ij^k, k=0..8
// Angular: q_ang[i,n,0] = S_n^2, S_n = sum_j fc r^n
//          q_ang[i,n,1] = |V_n|^2, V_n = sum_j fc r^(n-1) dr
//          q_ang[i,n,2] = 0.5*(3*||M_n||_F^2 - S_n^2), M_n = sum_j fc r^(n-2) dr(x)dr
//
// 2 warps per atom (split j-range), 2 atoms per 128-thread block, 96 blocks
// = one wave on 148 SMs with all 4 SMSPs busy. Fractional coords staged in
// shared memory; butterfly reduce within warp; smem combine across the warp
// pair; epilogue distributed over 18 lanes. (Session-best configuration:
// direct-global and barrier-restructured variants all measured equal or
// worse — this kernel is launch-overhead-bound at ~6.5us.)

#define BLOCK 128
#define MAXN 512
#define RCUT 6.0f

__global__ void __launch_bounds__(BLOCK)
desc_kernel(const float* __restrict__ R,
            const float* __restrict__ box,
            float* __restrict__ out, int N)
{
    __shared__ float s0[MAXN], s1[MAXN], s2[MAXN];
    __shared__ float sred[2][36];   // partial sums from the "sub==1" warp of each atom

    const int t    = threadIdx.x;
    const int lane = t & 31;
    const int warp = t >> 5;        // 0..3
    const int a    = warp >> 1;     // atom slot within block (0/1)
    const int sub  = warp & 1;      // which half of j-range
    const int i    = blockIdx.x * 2 + a;
    const bool valid = (i < N);

    // Box + inverse in registers (redundant per thread, cheap).
    float b[9];
#pragma unroll
    for (int k = 0; k < 9; k++) b[k] = __ldg(box + k);

    const bool diag = (b[1] == 0.f && b[2] == 0.f && b[3] == 0.f &&
                       b[5] == 0.f && b[6] == 0.f && b[7] == 0.f);

    const float det =
        b[0] * (b[4] * b[8] - b[5] * b[7]) -
        b[1] * (b[3] * b[8] - b[5] * b[6]) +
        b[2] * (b[3] * b[7] - b[4] * b[6]);
    const float idet = 1.0f / det;
    float inv[9];
    inv[0] = (b[4] * b[8] - b[5] * b[7]) * idet;
    inv[1] = (b[2] * b[7] - b[1] * b[8]) * idet;
    inv[2] = (b[1] * b[5] - b[2] * b[4]) * idet;
    inv[3] = (b[5] * b[6] - b[3] * b[8]) * idet;
    inv[4] = (b[0] * b[8] - b[2] * b[6]) * idet;
    inv[5] = (b[2] * b[3] - b[0] * b[5]) * idet;
    inv[6] = (b[3] * b[7] - b[4] * b[6]) * idet;
    inv[7] = (b[1] * b[6] - b[0] * b[7]) * idet;
    inv[8] = (b[0] * b[4] - b[1] * b[3]) * idet;

    // Fractional coordinates into shared (3 arrays: conflict-free LDS).
    if (diag) {
        const float i0 = inv[0], i4 = inv[4], i8 = inv[8];
        for (int j = t; j < N; j += BLOCK) {
            s0[j] = i0 * __ldg(R + 3 * j + 0);
            s1[j] = i4 * __ldg(R + 3 * j + 1);
            s2[j] = i8 * __ldg(R + 3 * j + 2);
        }
    } else {
        for (int j = t; j < N; j += BLOCK) {
            float x = __ldg(R + 3 * j + 0);
            float y = __ldg(R + 3 * j + 1);
            float z = __ldg(R + 3 * j + 2);
            s0[j] = inv[0] * x + inv[1] * y + inv[2] * z;
            s1[j] = inv[3] * x + inv[4] * y + inv[5] * z;
            s2[j] = inv[6] * x + inv[7] * y + inv[8] * z;
        }
    }
    __syncthreads();

    const float PI_OVER_RC = 3.14159265358979323846f / RCUT;

    // Accumulators: [0..8] radial (S_n = acc[n]); [9..17] V_n; [18..35] M_n.
    float acc[36];
#pragma unroll
    for (int k = 0; k < 36; k++) acc[k] = 0.0f;

    if (valid) {
        const float si0 = s0[i], si1 = s1[i], si2 = s2[i];
        const float b0 = b[0], b4 = b[4], b8 = b[8];

        for (int j = lane + 32 * sub; j < N; j += 64) {
            if (j == i) continue;
            float d0 = si0 - s0[j];
            float d1 = si1 - s1[j];
            float d2 = si2 - s2[j];
            d0 -= rintf(d0);   // minimum image (round-half-even = jnp.round)
            d1 -= rintf(d1);
            d2 -= rintf(d2);
            float dx, dy, dz;
            if (diag) {
                dx = b0 * d0; dy = b4 * d1; dz = b8 * d2;
            } else {
                dx = b[0] * d0 + b[1] * d1 + b[2] * d2;
                dy = b[3] * d0 + b[4] * d1 + b[5] * d2;
                dz = b[6] * d0 + b[7] * d1 + b[8] * d2;
            }
            float r2 = dx * dx + dy * dy + dz * dz;
            float invr = rsqrtf(r2);
            float r = r2 * invr;
            if (r >= RCUT) continue;   // fc exactly 0 there

            float fc = 0.5f * __cosf(r * PI_OVER_RC) + 0.5f;

            // Radial moments fc * r^k, k = 0..8 (log-depth powers)
            float rr2 = r * r;
            float rr3 = rr2 * r;
            float rr4 = rr2 * rr2;
            float fcr4 = fc * rr4;
            acc[0] += fc;
            acc[1] += fc * r;
            acc[2] += fc * rr2;
            acc[3] += fc * rr3;
            acc[4] += fcr4;
            acc[5] += fcr4 * r;
            acc[6] += fcr4 * rr2;
            acc[7] += fcr4 * rr3;
            acc[8] += fcr4 * rr4;

            // Angular moment weights: wv_n = fc r^(n-1), wm_n = fc r^(n-2)
            float wv0 = fc * invr;     // = wm1
            float wv2 = fc * r;
            float wm0 = wv0 * invr;
            float xx = dx * dx, xy = dx * dy, xz = dx * dz;
            float yy = dy * dy, yz = dy * dz, zz = dz * dz;

            acc[9]  += wv0 * dx;  acc[10] += wv0 * dy;  acc[11] += wv0 * dz;
            acc[12] += fc  * dx;  acc[13] += fc  * dy;  acc[14] += fc  * dz;
            acc[15] += wv2 * dx;  acc[16] += wv2 * dy;  acc[17] += wv2 * dz;

            acc[18] += wm0 * xx;  acc[19] += wm0 * xy;  acc[20] += wm0 * xz;
            acc[21] += wm0 * yy;  acc[22] += wm0 * yz;  acc[23] += wm0 * zz;
            acc[24] += wv0 * xx;  acc[25] += wv0 * xy;  acc[26] += wv0 * xz;
            acc[27] += wv0 * yy;  acc[28] += wv0 * yz;  acc[29] += wv0 * zz;
            acc[30] += fc  * xx;  acc[31] += fc  * xy;  acc[32] += fc  * xz;
            acc[33] += fc  * yy;  acc[34] += fc  * yz;  acc[35] += fc  * zz;
        }

        // Warp butterfly: afterwards EVERY lane holds all 36 sums.
#pragma unroll
        for (int k = 0; k < 36; k++) {
            float v = acc[k];
#pragma unroll
            for (int o = 16; o > 0; o >>= 1) v += __shfl_xor_sync(0xffffffffu, v, o);
            acc[k] = v;
        }
    }

    // Cross-warp combine: sub==1 warp publishes its 36 sums.
    if (sub == 1) {
        if (lane < 36) sred[a][lane] = acc[lane];
        if (lane < 4)  sred[a][32 + lane] = acc[32 + lane];
    }
    __syncthreads();

    if (valid && sub == 0 && lane < 18) {
#pragma unroll
        for (int k = 0; k < 36; k++) acc[k] += sred[a][k];   // broadcast LDS

        float* o = out + (size_t)i * 18;
        float val;
        if (lane < 9) {
            val = acc[lane];
        } else {
            int idx = lane - 9;
            int n = idx / 3;
            int l = idx - 3 * n;
            float s = acc[n];
            if (l == 0) {
                val = s * s;
            } else if (l == 1) {
                float vx = acc[9 + 3 * n], vy = acc[10 + 3 * n], vz = acc[11 + 3 * n];
                val = vx * vx + vy * vy + vz * vz;
            } else {
                float m0 = acc[18 + 6 * n], m1 = acc[19 + 6 * n], m2 = acc[20 + 6 * n];
                float m3 = acc[21 + 6 * n], m4 = acc[22 + 6 * n], m5 = acc[23 + 6 * n];
                float frob = m0 * m0 + m3 * m3 + m5 * m5 +
                             2.0f * (m1 * m1 + m2 * m2 + m4 * m4);
                val = 0.5f * (3.0f * frob - s * s);
            }
        }
        o[lane] = val;
    }
}

extern "C" void kernel_launch(void* const* d_in, const int* in_sizes, int n_in,
                              void* d_out, int out_size) {
    const float* R   = (const float*)d_in[0];   // [N,3] fp32
    // d_in[1] = Z (int32), unused by the reference math
    const float* box = (const float*)d_in[2];   // [3,3] fp32
    float* out = (float*)d_out;                 // [N,18] fp32
    const int N = in_sizes[0] / 3;
    const int blocks = (N + 1) / 2;             // 2 atoms per block
    desc_kernel<<<blocks, BLOCK>>>(R, box, out, N);
}

// round 14
// speedup vs baseline: 1.3349x; 1.3349x over previous
#include <cuda_runtime.h>
#include <cuda_bf16.h>
#include <math.h>

// DescriptorBuilder: periodic minimum-image descriptors (O(N^2) factorized).
// Radial:  q_r[i,k] = sum_j fc(r_ij) * r_ij^k, k=0..8
// Angular: q_ang[i,n,0] = S_n^2, S_n = sum_j fc r^n
//          q_ang[i,n,1] = |V_n|^2, V_n = sum_j fc r^(n-1) dr
//          q_ang[i,n,2] = 0.5*(3*||M_n||_F^2 - S_n^2), M_n = sum_j fc r^(n-2) dr(x)dr
//
// Leanest measured-good configuration (R8, 6.66us on its draw):
// 128 threads/block, 2 warps per atom (split j-range), 2 atoms per block,
// 96 blocks = one wave; float4-vectorized smem staging of raw coords;
// diagonal-box fast path; N==192 specialization with batched LDS; full warp
// butterfly; sub==1 publish; block barrier; 18-lane distributed epilogue.
// NOTE: harness timing is bimodal (identical binaries measured 6.56 and
// 8.93us) — the lean body minimizes expected time across clock draws.

#define BLOCK 128
#define MAXN 512
#define RCUT 6.0f

__global__ void __launch_bounds__(BLOCK)
desc_kernel(const float* __restrict__ R,
            const float* __restrict__ box,
            float* __restrict__ out, int N)
{
    __shared__ float sR[MAXN * 3];    // flat raw Cartesian coords
    __shared__ float sred[2][36];     // partial sums published by sub==1 warps

    const int t    = threadIdx.x;
    const int lane = t & 31;
    const int warp = t >> 5;        // 0..3
    const int a    = warp >> 1;     // atom slot (0/1)
    const int sub  = warp & 1;      // j-range half
    const int i    = blockIdx.x * 2 + a;
    const bool valid = (i < N);

    // ---- Vectorized staging: 3N floats via float4 ----
    {
        const int nflt = 3 * N;
        const int nvec = nflt >> 2;
        const float4* R4 = reinterpret_cast<const float4*>(R);
        float4* s4 = reinterpret_cast<float4*>(sR);
        for (int v = t; v < nvec; v += BLOCK) s4[v] = __ldg(R4 + v);
        for (int v = (nvec << 2) + t; v < nflt; v += BLOCK) sR[v] = __ldg(R + v);
    }

    // Box in registers; diagonal fast path avoids the 3x3 inverse.
    float b[9];
#pragma unroll
    for (int k = 0; k < 9; k++) b[k] = __ldg(box + k);

    const bool diag = (b[1] == 0.f && b[2] == 0.f && b[3] == 0.f &&
                       b[5] == 0.f && b[6] == 0.f && b[7] == 0.f);

    float inv[9];
    if (diag) {
        inv[0] = 1.0f / b[0];
        inv[4] = 1.0f / b[4];
        inv[8] = 1.0f / b[8];
    } else {
        const float det =
            b[0] * (b[4] * b[8] - b[5] * b[7]) -
            b[1] * (b[3] * b[8] - b[5] * b[6]) +
            b[2] * (b[3] * b[7] - b[4] * b[6]);
        const float idet = 1.0f / det;
        inv[0] = (b[4] * b[8] - b[5] * b[7]) * idet;
        inv[1] = (b[2] * b[7] - b[1] * b[8]) * idet;
        inv[2] = (b[1] * b[5] - b[2] * b[4]) * idet;
        inv[3] = (b[5] * b[6] - b[3] * b[8]) * idet;
        inv[4] = (b[0] * b[8] - b[2] * b[6]) * idet;
        inv[5] = (b[2] * b[3] - b[0] * b[5]) * idet;
        inv[6] = (b[3] * b[7] - b[4] * b[6]) * idet;
        inv[7] = (b[1] * b[6] - b[0] * b[7]) * idet;
        inv[8] = (b[0] * b[4] - b[1] * b[3]) * idet;
    }

    __syncthreads();   // staging complete

    const float PI_OVER_RC = 3.14159265358979323846f / RCUT;

    // Accumulators: [0..8] radial (S_n = acc[n]); [9..17] V_n; [18..35] M_n.
    float acc[36];
#pragma unroll
    for (int k = 0; k < 36; k++) acc[k] = 0.0f;

    if (valid) {
        const float rix = sR[3 * i + 0];
        const float riy = sR[3 * i + 1];
        const float riz = sR[3 * i + 2];
        const int j0 = lane + 32 * sub;

        // One pair-interaction body (accumulates into acc[]).
        auto body = [&](float cx, float cy, float cz, bool skip) {
            float dx, dy, dz;
            if (diag) {
                dx = cx - b[0] * rintf(inv[0] * cx);
                dy = cy - b[4] * rintf(inv[4] * cy);
                dz = cz - b[8] * rintf(inv[8] * cz);
            } else {
                float f0 = rintf(inv[0] * cx + inv[1] * cy + inv[2] * cz);
                float f1 = rintf(inv[3] * cx + inv[4] * cy + inv[5] * cz);
                float f2 = rintf(inv[6] * cx + inv[7] * cy + inv[8] * cz);
                dx = cx - (b[0] * f0 + b[1] * f1 + b[2] * f2);
                dy = cy - (b[3] * f0 + b[4] * f1 + b[5] * f2);
                dz = cz - (b[6] * f0 + b[7] * f1 + b[8] * f2);
            }
            float r2 = dx * dx + dy * dy + dz * dz;
            float invr = rsqrtf(r2);
            float r = r2 * invr;
            if (skip || r >= RCUT) return;   // fc exactly 0 at/beyond cutoff

            float fc = 0.5f * __cosf(r * PI_OVER_RC) + 0.5f;

            float rr2 = r * r;
            float rr3 = rr2 * r;
            float rr4 = rr2 * rr2;
            float fcr4 = fc * rr4;
            acc[0] += fc;
            acc[1] += fc * r;
            acc[2] += fc * rr2;
            acc[3] += fc * rr3;
            acc[4] += fcr4;
            acc[5] += fcr4 * r;
            acc[6] += fcr4 * rr2;
            acc[7] += fcr4 * rr3;
            acc[8] += fcr4 * rr4;

            float wv0 = fc * invr;
            float wv2 = fc * r;
            float wm0 = wv0 * invr;
            float xx = dx * dx, xy = dx * dy, xz = dx * dz;
            float yy = dy * dy, yz = dy * dz, zz = dz * dz;

            acc[9]  += wv0 * dx;  acc[10] += wv0 * dy;  acc[11] += wv0 * dz;
            acc[12] += fc  * dx;  acc[13] += fc  * dy;  acc[14] += fc  * dz;
            acc[15] += wv2 * dx;  acc[16] += wv2 * dy;  acc[17] += wv2 * dz;

            acc[18] += wm0 * xx;  acc[19] += wm0 * xy;  acc[20] += wm0 * xz;
            acc[21] += wm0 * yy;  acc[22] += wm0 * yz;  acc[23] += wm0 * zz;
            acc[24] += wv0 * xx;  acc[25] += wv0 * xy;  acc[26] += wv0 * xz;
            acc[27] += wv0 * yy;  acc[28] += wv0 * yz;  acc[29] += wv0 * zz;
            acc[30] += fc  * xx;  acc[31] += fc  * xy;  acc[32] += fc  * xz;
            acc[33] += fc  * yy;  acc[34] += fc  * yz;  acc[35] += fc  * zz;
        };

        if (N == 192) {
            // Exactly 3 iterations per lane: batch all 9 LDS up front.
            const int ja = j0, jb = j0 + 64, jc = j0 + 128;
            float ax = sR[3 * ja], ay = sR[3 * ja + 1], az = sR[3 * ja + 2];
            float bx = sR[3 * jb], by = sR[3 * jb + 1], bz = sR[3 * jb + 2];
            float cx_ = sR[3 * jc], cy_ = sR[3 * jc + 1], cz_ = sR[3 * jc + 2];
            body(rix - ax,  riy - ay,  riz - az,  ja == i);
            body(rix - bx,  riy - by,  riz - bz,  jb == i);
            body(rix - cx_, riy - cy_, riz - cz_, jc == i);
        } else {
            for (int j = j0; j < N; j += 64) {
                body(rix - sR[3 * j], riy - sR[3 * j + 1], riz - sR[3 * j + 2],
                     j == i);
            }
        }

        // Full warp butterfly: afterwards EVERY lane holds all 36 sums.
#pragma unroll
        for (int k = 0; k < 36; k++) {
            float v = acc[k];
#pragma unroll
            for (int o = 16; o > 0; o >>= 1) v += __shfl_xor_sync(0xffffffffu, v, o);
            acc[k] = v;
        }
    }

    // Cross-warp combine: sub==1 warp publishes its 36 sums.
    if (sub == 1) {
        if (lane < 36) sred[a][lane] = acc[lane];
        if (lane < 4)  sred[a][32 + lane] = acc[32 + lane];
    }
    __syncthreads();

    // Epilogue: 18 lanes of the sub==0 warp combine + write.
    if (valid && sub == 0 && lane < 18) {
#pragma unroll
        for (int k = 0; k < 36; k++) acc[k] += sred[a][k];   // broadcast LDS

        float val;
        if (lane < 9) {
            val = acc[lane];
        } else {
            int idx = lane - 9;
            int n = idx / 3;
            int l = idx - 3 * n;
            float s = acc[n];
            if (l == 0) {
                val = s * s;
            } else if (l == 1) {
                float vx = acc[9 + 3 * n], vy = acc[10 + 3 * n], vz = acc[11 + 3 * n];
                val = vx * vx + vy * vy + vz * vz;
            } else {
                float m0 = acc[18 + 6 * n], m1 = acc[19 + 6 * n], m2 = acc[20 + 6 * n];
                float m3 = acc[21 + 6 * n], m4 = acc[22 + 6 * n], m5 = acc[23 + 6 * n];
                float frob = m0 * m0 + m3 * m3 + m5 * m5 +
                             2.0f * (m1 * m1 + m2 * m2 + m4 * m4);
                val = 0.5f * (3.0f * frob - s * s);
            }
        }
        out[(size_t)i * 18 + lane] = val;
    }
}

extern "C" void kernel_launch(void* const* d_in, const int* in_sizes, int n_in,
                              void* d_out, int out_size) {
    const float* R   = (const float*)d_in[0];   // [N,3] fp32
    // d_in[1] = Z (int32), unused by the reference math
    const float* box = (const float*)d_in[2];   // [3,3] fp32
    float* out = (float*)d_out;                 // [N,18] fp32
    const int N = in_sizes[0] / 3;
    const int blocks = (N + 1) / 2;             // 2 atoms per block
    desc_kernel<<<blocks, BLOCK>>>(R, box, out, N);
}